// round 1
// baseline (speedup 1.0000x reference)
#include <cuda_runtime.h>

#define SEQ 262144
#define IN  100
#define HID 40

// scratch (allocation-free rule: __device__ globals)
__device__ float g_A[SEQ * HID];   // a_i = Wx @ x_i
__device__ float g_T[SEQ * HID];   // t_i trace for phase 3

typedef unsigned long long u64;

__device__ __forceinline__ u64 pack2(float lo, float hi) {
    u64 r; asm("mov.b64 %0, {%1,%2};" : "=l"(r) : "f"(lo), "f"(hi)); return r;
}
__device__ __forceinline__ void unpack2(u64 v, float& lo, float& hi) {
    asm("mov.b64 {%0,%1}, %2;" : "=f"(lo), "=f"(hi) : "l"(v));
}
__device__ __forceinline__ u64 fma2(u64 a, u64 b, u64 c) {
    u64 d; asm("fma.rn.f32x2 %0, %1, %2, %3;" : "=l"(d) : "l"(a), "l"(b), "l"(c)); return d;
}
__device__ __forceinline__ u64 add2(u64 a, u64 b) {
    u64 d; asm("add.rn.f32x2 %0, %1, %2;" : "=l"(d) : "l"(a), "l"(b)); return d;
}
__device__ __forceinline__ float hadd2(u64 v) {
    float lo, hi; unpack2(v, lo, hi); return lo + hi;
}

// tanh(x) = 1 - 2/(exp(2x)+1); MUFU.EX2 + MUFU.RCP based, ~1e-6 rel err,
// saturates correctly at +/-1 for large |x| (exp -> inf or 0).
__device__ __forceinline__ float tanh_fast(float x) {
    float e = __expf(2.0f * x);
    return 1.0f - __fdividef(2.0f, e + 1.0f);
}

// ============================================================================
// Phase 1: g_A[i][j] = sum_k Wx[j][k] * s[i][k]   (fully parallel)
// One warp per block; lane = timestep within a 32-step tile.
// x rows staged in shared transposed as f32x2 pairs (conflict-light),
// Wx rows read as uniform-address LDS broadcasts.
// ============================================================================
__global__ void __launch_bounds__(32) phase1_kernel(
    const float* __restrict__ s, const float* __restrict__ Wx)
{
    __shared__ __align__(16) float wx[HID * IN];   // 16000 B
    __shared__ u64 xs[IN / 2][32];                 // 12800 B, xs[k2][lane]

    const int lane = threadIdx.x;

    // cooperative load of Wx (1000 float4)
    const float4* wsrc = (const float4*)Wx;
    float4* wdst = (float4*)wx;
    for (int t = lane; t < (HID * IN) / 4; t += 32) wdst[t] = wsrc[t];

    const int i = blockIdx.x * 32 + lane;
    const float4* xr = (const float4*)(s + (size_t)i * IN);
#pragma unroll
    for (int c = 0; c < IN / 4; ++c) {
        float4 v = xr[c];
        xs[2 * c][lane]     = pack2(v.x, v.y);
        xs[2 * c + 1][lane] = pack2(v.z, v.w);
    }
    __syncthreads();

    float* Ao = g_A + (size_t)i * HID;
#pragma unroll 1
    for (int j = 0; j < HID; ++j) {
        const u64* wrow = (const u64*)(wx + j * IN);  // 400j bytes, 8-aligned
        u64 acc[4] = {0, 0, 0, 0};
#pragma unroll
        for (int k = 0; k < IN / 2; ++k) {
            acc[k & 3] = fma2(wrow[k], xs[k][lane], acc[k & 3]);
        }
        Ao[j] = hadd2(add2(add2(acc[0], acc[1]), add2(acc[2], acc[3])));
    }
}

// ============================================================================
// Phase 2: serial recurrence, single warp.
// Lane j owns Wh row j (and row 32+j for j<8) entirely in registers as
// f32x2 pairs. t double-buffered in shared; exactly one __syncwarp per step.
// a_i prefetched 4 steps ahead into a register ring.
// ============================================================================
__global__ void __launch_bounds__(32) phase2_kernel(
    const float* __restrict__ init, const float* __restrict__ Wh,
    float* __restrict__ tfinal)
{
    __shared__ __align__(16) float tsh[2][HID];

    const int j = threadIdx.x;
    const bool hasB = (j < 8);

    // preload Wh rows into registers
    u64 whA[HID / 2], whB[HID / 2];
    const u64* WA = (const u64*)(Wh + j * HID);
    const u64* WB = (const u64*)(Wh + (32 + j) * HID);
#pragma unroll
    for (int p = 0; p < HID / 2; ++p) {
        whA[p] = WA[p];
        whB[p] = hasB ? WB[p] : 0ull;
    }

    tsh[0][j] = init[j];
    if (hasB) tsh[0][32 + j] = init[32 + j];

    // prefetch ring for a_i (depth 4)
    float aA[4], aB[4];
#pragma unroll
    for (int d = 0; d < 4; ++d) {
        aA[d] = g_A[d * HID + j];
        aB[d] = hasB ? g_A[d * HID + 32 + j] : 0.0f;
    }
    __syncwarp();

    float outA = 0.0f, outB = 0.0f;

#pragma unroll 4
    for (int i = 0; i < SEQ; ++i) {
        const int rb = i & 1;
        const float4* tb = (const float4*)tsh[rb];

        u64 accA[4] = {0, 0, 0, 0};
        u64 accB[4] = {0, 0, 0, 0};
#pragma unroll
        for (int p = 0; p < 10; ++p) {
            float4 tv = tb[p];                      // broadcast LDS.128
            u64 t01 = pack2(tv.x, tv.y);
            u64 t23 = pack2(tv.z, tv.w);
            accA[(2 * p) & 3]     = fma2(whA[2 * p],     t01, accA[(2 * p) & 3]);
            accA[(2 * p + 1) & 3] = fma2(whA[2 * p + 1], t23, accA[(2 * p + 1) & 3]);
            accB[(2 * p) & 3]     = fma2(whB[2 * p],     t01, accB[(2 * p) & 3]);
            accB[(2 * p + 1) & 3] = fma2(whB[2 * p + 1], t23, accB[(2 * p + 1) & 3]);
        }

        const int slot = i & 3;
        float sA = hadd2(add2(add2(accA[0], accA[1]), add2(accA[2], accA[3]))) + aA[slot];
        float sB = hadd2(add2(add2(accB[0], accB[1]), add2(accB[2], accB[3]))) + aB[slot];

        // prefetch a_{i+4}
        const int ip = i + 4;
        if (ip < SEQ) {
            aA[slot] = g_A[ip * HID + j];
            aB[slot] = hasB ? g_A[ip * HID + 32 + j] : 0.0f;
        }

        outA = tanh_fast(sA);
        outB = tanh_fast(sB);

        tsh[rb ^ 1][j] = outA;
        if (hasB) tsh[rb ^ 1][32 + j] = outB;

        g_T[(size_t)i * HID + j] = outA;
        if (hasB) g_T[(size_t)i * HID + 32 + j] = outB;

        __syncwarp();
    }

    tfinal[j] = outA;
    if (hasB) tfinal[32 + j] = outB;
}

// ============================================================================
// Phase 3: y_i = softmax(Wy @ t_i)  (fully parallel)
// One warp per timestep (grid-stride). Wy staged in shared with row pad 42
// (2-way LDS conflicts max). t_i loaded as broadcast LDG.128 into registers.
// ============================================================================
#define WYPAD 42
__global__ void __launch_bounds__(256) phase3_kernel(
    const float* __restrict__ Wy, float* __restrict__ ys)
{
    __shared__ __align__(8) float wy[IN * WYPAD];

    const int tid = threadIdx.x;
    for (int t = tid; t < IN * HID; t += 256) {
        int jr = t / HID, kr = t % HID;
        wy[jr * WYPAD + kr] = Wy[t];
    }
    __syncthreads();

    const int lane = tid & 31;
    const int warp = blockIdx.x * 8 + (tid >> 5);
    const int nwarp = gridDim.x * 8;

    for (int i = warp; i < SEQ; i += nwarp) {
        const float4* tp = (const float4*)(g_T + (size_t)i * HID);
        u64 t2[HID / 2];
#pragma unroll
        for (int p = 0; p < 10; ++p) {
            float4 v = tp[p];
            t2[2 * p]     = pack2(v.x, v.y);
            t2[2 * p + 1] = pack2(v.z, v.w);
        }

        float z[4];
#pragma unroll
        for (int o = 0; o < 4; ++o) {
            const int jj = lane + 32 * o;
            if (jj < IN) {
                const u64* wr = (const u64*)(wy + jj * WYPAD); // 168B stride, 8-aligned
                u64 acc[4] = {0, 0, 0, 0};
#pragma unroll
                for (int p = 0; p < HID / 2; ++p)
                    acc[p & 3] = fma2(wr[p], t2[p], acc[p & 3]);
                z[o] = hadd2(add2(add2(acc[0], acc[1]), add2(acc[2], acc[3])));
            } else {
                z[o] = -1e30f;
            }
        }

        float m = fmaxf(fmaxf(z[0], z[1]), fmaxf(z[2], z[3]));
#pragma unroll
        for (int off = 16; off; off >>= 1)
            m = fmaxf(m, __shfl_xor_sync(0xffffffffu, m, off));

        float e[4];
        float ssum = 0.0f;
#pragma unroll
        for (int o = 0; o < 4; ++o) {
            const int jj = lane + 32 * o;
            e[o] = (jj < IN) ? __expf(z[o] - m) : 0.0f;
            ssum += e[o];
        }
#pragma unroll
        for (int off = 16; off; off >>= 1)
            ssum += __shfl_xor_sync(0xffffffffu, ssum, off);

        const float r = __fdividef(1.0f, ssum);
        float* yo = ys + (size_t)i * IN;
#pragma unroll
        for (int o = 0; o < 4; ++o) {
            const int jj = lane + 32 * o;
            if (jj < IN) yo[jj] = e[o] * r;
        }
    }
}

// ============================================================================
// inputs (metadata order): s[SEQ*IN] f32, initialState[HID] f32,
//                          Wx[HID*IN] f32, Wh[HID*HID] f32, Wy[IN*HID] f32
// output: t_final[HID] then ys[SEQ*IN], float32
// ============================================================================
extern "C" void kernel_launch(void* const* d_in, const int* in_sizes, int n_in,
                              void* d_out, int out_size)
{
    const float* s    = (const float*)d_in[0];
    const float* init = (const float*)d_in[1];
    const float* Wx   = (const float*)d_in[2];
    const float* Wh   = (const float*)d_in[3];
    const float* Wy   = (const float*)d_in[4];
    float* out = (float*)d_out;

    phase1_kernel<<<SEQ / 32, 32>>>(s, Wx);
    phase2_kernel<<<1, 32>>>(init, Wh, out);          // writes out[0..39] + g_T
    phase3_kernel<<<2048, 256>>>(Wy, out + HID);      // writes ys
}

// round 2
// speedup vs baseline: 1.2884x; 1.2884x over previous
#include <cuda_runtime.h>

#define SEQ 262144
#define IN  100
#define HID 40

// scratch (allocation-free rule: __device__ globals). g_A padded so the
// phase-2 prefetch ring can read 4 steps past the end unguarded.
__device__ float g_A[SEQ * HID + 4 * HID + 64];   // a_i = Wx @ x_i (pre-scaled by 2*log2e)
__device__ float g_T[SEQ * HID];                  // t_i trace for phase 3

typedef unsigned long long u64;

__device__ __forceinline__ u64 pack2(float lo, float hi) {
    u64 r; asm("mov.b64 %0, {%1,%2};" : "=l"(r) : "f"(lo), "f"(hi)); return r;
}
__device__ __forceinline__ void unpack2(u64 v, float& lo, float& hi) {
    asm("mov.b64 {%0,%1}, %2;" : "=f"(lo), "=f"(hi) : "l"(v));
}
__device__ __forceinline__ u64 fma2(u64 a, u64 b, u64 c) {
    u64 d; asm("fma.rn.f32x2 %0, %1, %2, %3;" : "=l"(d) : "l"(a), "l"(b), "l"(c)); return d;
}
__device__ __forceinline__ u64 add2(u64 a, u64 b) {
    u64 d; asm("add.rn.f32x2 %0, %1, %2;" : "=l"(d) : "l"(a), "l"(b)); return d;
}
__device__ __forceinline__ float hadd2(u64 v) {
    float lo, hi; unpack2(v, lo, hi); return lo + hi;
}
__device__ __forceinline__ float ex2f(float x) {
    float r; asm("ex2.approx.f32 %0, %1;" : "=f"(r) : "f"(x)); return r;
}
__device__ __forceinline__ float rcpf(float x) {
    float r; asm("rcp.approx.f32 %0, %1;" : "=f"(r) : "f"(x)); return r;
}

// tanh(x) given v = 2*log2(e)*x already computed:
//   tanh(x) = 1 - 2/(2^v + 1)
__device__ __forceinline__ float tanh_from_scaled(float v) {
    float e = ex2f(v);
    float r = rcpf(e + 1.0f);
    return fmaf(-2.0f, r, 1.0f);
}

// tanh(x) = 1 - 2/(exp(2x)+1) for phase-agnostic use
__device__ __forceinline__ float tanh_fast(float x) {
    float e = __expf(2.0f * x);
    return 1.0f - __fdividef(2.0f, e + 1.0f);
}

#define C2LOG2E 2.8853900817779268f   // 2*log2(e)

// ============================================================================
// Phase 1: g_A[i][j] = C2LOG2E * sum_k Wx[j][k] * s[i][k]   (fully parallel)
// One warp per block; lane = timestep within a 32-step tile.
// ============================================================================
__global__ void __launch_bounds__(32) phase1_kernel(
    const float* __restrict__ s, const float* __restrict__ Wx)
{
    __shared__ __align__(16) float wx[HID * IN];   // 16000 B
    __shared__ u64 xs[IN / 2][32];                 // 12800 B, xs[k2][lane]

    const int lane = threadIdx.x;

    const float4* wsrc = (const float4*)Wx;
    float4* wdst = (float4*)wx;
    for (int t = lane; t < (HID * IN) / 4; t += 32) wdst[t] = wsrc[t];

    const int i = blockIdx.x * 32 + lane;
    const float4* xr = (const float4*)(s + (size_t)i * IN);
#pragma unroll
    for (int c = 0; c < IN / 4; ++c) {
        float4 v = xr[c];
        xs[2 * c][lane]     = pack2(v.x, v.y);
        xs[2 * c + 1][lane] = pack2(v.z, v.w);
    }
    __syncthreads();

    float* Ao = g_A + (size_t)i * HID;
#pragma unroll 1
    for (int j = 0; j < HID; ++j) {
        const u64* wrow = (const u64*)(wx + j * IN);
        u64 acc[4] = {0, 0, 0, 0};
#pragma unroll
        for (int k = 0; k < IN / 2; ++k) {
            acc[k & 3] = fma2(wrow[k], xs[k][lane], acc[k & 3]);
        }
        Ao[j] = C2LOG2E * hadd2(add2(add2(acc[0], acc[1]), add2(acc[2], acc[3])));
    }
}

// ============================================================================
// Phase 2: serial recurrence. 64 threads (2 warps), thread j < 40 owns
// output j. Wh row j held in registers PRE-SCALED by 2*log2e; a_i already
// pre-scaled by phase 1. t double-buffered in shared, read as ulonglong2
// (LDS.128 -> b64 pairs, zero pack MOVs). One __syncthreads per step.
// ============================================================================
__global__ void __launch_bounds__(64) phase2_kernel(
    const float* __restrict__ init, const float* __restrict__ Wh,
    float* __restrict__ tfinal)
{
    __shared__ __align__(16) float tsh[2][64];

    const int j  = threadIdx.x;
    const int jr = (j < HID) ? j : 0;          // clamp for OOB-safe loads
    const bool act = (j < HID);

    // preload Wh row jr, scaled by 2*log2e
    u64 wh[HID / 2];
    const float2* wr = (const float2*)(Wh + jr * HID);
#pragma unroll
    for (int p = 0; p < HID / 2; ++p) {
        float2 w = wr[p];
        wh[p] = pack2(w.x * C2LOG2E, w.y * C2LOG2E);
    }

    tsh[0][j] = act ? init[j] : 0.0f;
    tsh[1][j] = 0.0f;

    // prefetch ring for a (already scaled), depth 4
    const float* ap = g_A + jr;
    float a[4];
#pragma unroll
    for (int d = 0; d < 4; ++d) a[d] = ap[d * HID];
    ap += 4 * HID;

    __syncthreads();

    float outv = tsh[0][j];
    float* gT = g_T + jr;

#pragma unroll 4
    for (int i = 0; i < SEQ; ++i) {
        const int rb   = i & 1;
        const int slot = i & 3;
        const ulonglong2* tb = (const ulonglong2*)tsh[rb];

        u64 acc0 = pack2(a[slot], 0.0f);
        u64 acc1 = 0, acc2 = 0, acc3 = 0;

        // prefetch a_{i+4} (padded array; no bounds check)
        a[slot] = ap[0];
        ap += HID;

#pragma unroll
        for (int p = 0; p < 5; ++p) {
            ulonglong2 q0 = tb[2 * p];
            ulonglong2 q1 = tb[2 * p + 1];
            acc0 = fma2(wh[4 * p],     q0.x, acc0);
            acc1 = fma2(wh[4 * p + 1], q0.y, acc1);
            acc2 = fma2(wh[4 * p + 2], q1.x, acc2);
            acc3 = fma2(wh[4 * p + 3], q1.y, acc3);
        }

        u64 r01 = add2(acc0, acc1);
        u64 r23 = add2(acc2, acc3);
        float v = hadd2(add2(r01, r23));

        outv = tanh_from_scaled(v);

        tsh[rb ^ 1][j] = outv;
        if (act) gT[(size_t)i * HID] = outv;

        __syncthreads();
    }

    if (act) tfinal[j] = outv;
}

// ============================================================================
// Phase 3: y_i = softmax(Wy @ t_i)  (fully parallel, one warp per timestep)
// ============================================================================
#define WYPAD 42
__global__ void __launch_bounds__(256) phase3_kernel(
    const float* __restrict__ Wy, float* __restrict__ ys)
{
    __shared__ __align__(8) float wy[IN * WYPAD];

    const int tid = threadIdx.x;
    for (int t = tid; t < IN * HID; t += 256) {
        int jrow = t / HID, kr = t % HID;
        wy[jrow * WYPAD + kr] = Wy[t];
    }
    __syncthreads();

    const int lane = tid & 31;
    const int warp = blockIdx.x * 8 + (tid >> 5);
    const int nwarp = gridDim.x * 8;

    for (int i = warp; i < SEQ; i += nwarp) {
        const ulonglong2* tp = (const ulonglong2*)(g_T + (size_t)i * HID);
        u64 t2[HID / 2];
#pragma unroll
        for (int p = 0; p < 10; ++p) {
            ulonglong2 v = tp[p];
            t2[2 * p]     = v.x;
            t2[2 * p + 1] = v.y;
        }

        float z[4];
#pragma unroll
        for (int o = 0; o < 4; ++o) {
            const int jj = lane + 32 * o;
            if (jj < IN) {
                const u64* wrow = (const u64*)(wy + jj * WYPAD);
                u64 acc[4] = {0, 0, 0, 0};
#pragma unroll
                for (int p = 0; p < HID / 2; ++p)
                    acc[p & 3] = fma2(wrow[p], t2[p], acc[p & 3]);
                z[o] = hadd2(add2(add2(acc[0], acc[1]), add2(acc[2], acc[3])));
            } else {
                z[o] = -1e30f;
            }
        }

        float m = fmaxf(fmaxf(z[0], z[1]), fmaxf(z[2], z[3]));
#pragma unroll
        for (int off = 16; off; off >>= 1)
            m = fmaxf(m, __shfl_xor_sync(0xffffffffu, m, off));

        float e[4];
        float ssum = 0.0f;
#pragma unroll
        for (int o = 0; o < 4; ++o) {
            const int jj = lane + 32 * o;
            e[o] = (jj < IN) ? __expf(z[o] - m) : 0.0f;
            ssum += e[o];
        }
#pragma unroll
        for (int off = 16; off; off >>= 1)
            ssum += __shfl_xor_sync(0xffffffffu, ssum, off);

        const float r = __fdividef(1.0f, ssum);
        float* yo = ys + (size_t)i * IN;
#pragma unroll
        for (int o = 0; o < 4; ++o) {
            const int jj = lane + 32 * o;
            if (jj < IN) yo[jj] = e[o] * r;
        }
    }
}

// ============================================================================
// inputs (metadata order): s[SEQ*IN] f32, initialState[HID] f32,
//                          Wx[HID*IN] f32, Wh[HID*HID] f32, Wy[IN*HID] f32
// output: t_final[HID] then ys[SEQ*IN], float32
// ============================================================================
extern "C" void kernel_launch(void* const* d_in, const int* in_sizes, int n_in,
                              void* d_out, int out_size)
{
    const float* s    = (const float*)d_in[0];
    const float* init = (const float*)d_in[1];
    const float* Wx   = (const float*)d_in[2];
    const float* Wh   = (const float*)d_in[3];
    const float* Wy   = (const float*)d_in[4];
    float* out = (float*)d_out;

    phase1_kernel<<<SEQ / 32, 32>>>(s, Wx);
    phase2_kernel<<<1, 64>>>(init, Wh, out);          // writes out[0..39] + g_T
    phase3_kernel<<<2048, 256>>>(Wy, out + HID);      // writes ys
}

// round 3
// speedup vs baseline: 1.3334x; 1.0350x over previous
#include <cuda_runtime.h>

#define SEQ 262144
#define IN  100
#define HID 40

// scratch (allocation-free rule: __device__ globals). g_A padded so the
// phase-2 prefetch ring can read 4 steps past the end unguarded.
__device__ float g_A[SEQ * HID + 4 * HID + 64];   // a_i = Wx @ x_i (pre-scaled by 2*log2e)
__device__ float g_T[SEQ * HID];                  // t_i trace for phase 3

typedef unsigned long long u64;

__device__ __forceinline__ u64 pack2(float lo, float hi) {
    u64 r; asm("mov.b64 %0, {%1,%2};" : "=l"(r) : "f"(lo), "f"(hi)); return r;
}
__device__ __forceinline__ void unpack2(u64 v, float& lo, float& hi) {
    asm("mov.b64 {%0,%1}, %2;" : "=f"(lo), "=f"(hi) : "l"(v));
}
__device__ __forceinline__ u64 fma2(u64 a, u64 b, u64 c) {
    u64 d; asm("fma.rn.f32x2 %0, %1, %2, %3;" : "=l"(d) : "l"(a), "l"(b), "l"(c)); return d;
}
__device__ __forceinline__ u64 add2(u64 a, u64 b) {
    u64 d; asm("add.rn.f32x2 %0, %1, %2;" : "=l"(d) : "l"(a), "l"(b)); return d;
}
__device__ __forceinline__ float hadd2(u64 v) {
    float lo, hi; unpack2(v, lo, hi); return lo + hi;
}
__device__ __forceinline__ float ex2f(float x) {
    float r; asm("ex2.approx.f32 %0, %1;" : "=f"(r) : "f"(x)); return r;
}
__device__ __forceinline__ float rcpf(float x) {
    float r; asm("rcp.approx.f32 %0, %1;" : "=f"(r) : "f"(x)); return r;
}

// tanh(x) given v = 2*log2(e)*x already computed: tanh(x) = 1 - 2/(2^v + 1)
__device__ __forceinline__ float tanh_from_scaled(float v) {
    float e = ex2f(v);
    float r = rcpf(e + 1.0f);
    return fmaf(-2.0f, r, 1.0f);
}

#define C2LOG2E 2.8853900817779268f   // 2*log2(e)

// ============================================================================
// Phase 1: g_A[i][j] = C2LOG2E * sum_k Wx[j][k] * s[i][k]   (fully parallel)
// ============================================================================
__global__ void __launch_bounds__(32) phase1_kernel(
    const float* __restrict__ s, const float* __restrict__ Wx)
{
    __shared__ __align__(16) float wx[HID * IN];   // 16000 B
    __shared__ u64 xs[IN / 2][32];                 // 12800 B

    const int lane = threadIdx.x;

    const float4* wsrc = (const float4*)Wx;
    float4* wdst = (float4*)wx;
    for (int t = lane; t < (HID * IN) / 4; t += 32) wdst[t] = wsrc[t];

    const int i = blockIdx.x * 32 + lane;
    const float4* xr = (const float4*)(s + (size_t)i * IN);
#pragma unroll
    for (int c = 0; c < IN / 4; ++c) {
        float4 v = xr[c];
        xs[2 * c][lane]     = pack2(v.x, v.y);
        xs[2 * c + 1][lane] = pack2(v.z, v.w);
    }
    __syncthreads();

    float* Ao = g_A + (size_t)i * HID;
#pragma unroll 1
    for (int j = 0; j < HID; ++j) {
        const u64* wrow = (const u64*)(wx + j * IN);
        u64 acc[4] = {0, 0, 0, 0};
#pragma unroll
        for (int k = 0; k < IN / 2; ++k) {
            acc[k & 3] = fma2(wrow[k], xs[k][lane], acc[k & 3]);
        }
        Ao[j] = C2LOG2E * hadd2(add2(add2(acc[0], acc[1]), add2(acc[2], acc[3])));
    }
}

// ============================================================================
// Phase 2: serial recurrence. 64 threads (2 warps), thread j < 40 owns
// output j. Key change this round: ALL 10 LDS.128 of the t vector are
// issued back-to-back into registers BEFORE any fma2 touches them, so the
// shared-memory latency is paid once (~50cy) instead of 10x serialized.
// ============================================================================
__global__ void __launch_bounds__(64, 1) phase2_kernel(
    const float* __restrict__ init, const float* __restrict__ Wh,
    float* __restrict__ tfinal)
{
    __shared__ __align__(16) float tsh[2][64];

    const int j  = threadIdx.x;
    const int jr = (j < HID) ? j : 0;          // clamp for OOB-safe loads
    const bool act = (j < HID);

    // preload Wh row jr, scaled by 2*log2e
    u64 wh[HID / 2];
    const float2* wr = (const float2*)(Wh + jr * HID);
#pragma unroll
    for (int p = 0; p < HID / 2; ++p) {
        float2 w = wr[p];
        wh[p] = pack2(w.x * C2LOG2E, w.y * C2LOG2E);
    }

    tsh[0][j] = act ? init[j] : 0.0f;
    tsh[1][j] = 0.0f;

    // prefetch ring for a (already scaled), depth 4
    const float* ap = g_A + jr;
    float a[4];
#pragma unroll
    for (int d = 0; d < 4; ++d) a[d] = ap[d * HID];
    ap += 4 * HID;

    __syncthreads();

    float outv = tsh[0][j];
    float* gT = g_T + jr;

#pragma unroll 4
    for (int i = 0; i < SEQ; ++i) {
        const int rb   = i & 1;
        const int slot = i & 3;
        const ulonglong2* tb = (const ulonglong2*)tsh[rb];

        // ---- batched loads: 10x LDS.128, no consumer in between ----
        u64 q[HID / 2];
#pragma unroll
        for (int p = 0; p < 10; ++p) {
            ulonglong2 v = tb[p];
            q[2 * p]     = v.x;
            q[2 * p + 1] = v.y;
        }

        // prefetch a_{i+4} (padded array; off critical path)
        float anew = ap[0];
        ap += HID;

        // ---- 4 independent fma2 chains, depth 5 ----
        u64 acc0 = fma2(wh[0], q[0], pack2(a[slot], 0.0f));
        u64 acc1 = fma2(wh[1], q[1], 0ull);
        u64 acc2 = fma2(wh[2], q[2], 0ull);
        u64 acc3 = fma2(wh[3], q[3], 0ull);
#pragma unroll
        for (int p = 1; p < 5; ++p) {
            acc0 = fma2(wh[4 * p],     q[4 * p],     acc0);
            acc1 = fma2(wh[4 * p + 1], q[4 * p + 1], acc1);
            acc2 = fma2(wh[4 * p + 2], q[4 * p + 2], acc2);
            acc3 = fma2(wh[4 * p + 3], q[4 * p + 3], acc3);
        }
        a[slot] = anew;

        float v = hadd2(add2(add2(acc0, acc1), add2(acc2, acc3)));

        outv = tanh_from_scaled(v);

        tsh[rb ^ 1][j] = outv;
        if (act) gT[(size_t)i * HID] = outv;

        __syncthreads();
    }

    if (act) tfinal[j] = outv;
}

// ============================================================================
// Phase 3: y_i = softmax(Wy @ t_i)  (fully parallel, one warp per timestep)
// ============================================================================
#define WYPAD 42
__global__ void __launch_bounds__(256) phase3_kernel(
    const float* __restrict__ Wy, float* __restrict__ ys)
{
    __shared__ __align__(8) float wy[IN * WYPAD];

    const int tid = threadIdx.x;
    for (int t = tid; t < IN * HID; t += 256) {
        int jrow = t / HID, kr = t % HID;
        wy[jrow * WYPAD + kr] = Wy[t];
    }
    __syncthreads();

    const int lane = tid & 31;
    const int warp = blockIdx.x * 8 + (tid >> 5);
    const int nwarp = gridDim.x * 8;

    for (int i = warp; i < SEQ; i += nwarp) {
        const ulonglong2* tp = (const ulonglong2*)(g_T + (size_t)i * HID);
        u64 t2[HID / 2];
#pragma unroll
        for (int p = 0; p < 10; ++p) {
            ulonglong2 v = tp[p];
            t2[2 * p]     = v.x;
            t2[2 * p + 1] = v.y;
        }

        float z[4];
#pragma unroll
        for (int o = 0; o < 4; ++o) {
            const int jj = lane + 32 * o;
            if (jj < IN) {
                const u64* wrow = (const u64*)(wy + jj * WYPAD);
                u64 acc[4] = {0, 0, 0, 0};
#pragma unroll
                for (int p = 0; p < HID / 2; ++p)
                    acc[p & 3] = fma2(wrow[p], t2[p], acc[p & 3]);
                z[o] = hadd2(add2(add2(acc[0], acc[1]), add2(acc[2], acc[3])));
            } else {
                z[o] = -1e30f;
            }
        }

        float m = fmaxf(fmaxf(z[0], z[1]), fmaxf(z[2], z[3]));
#pragma unroll
        for (int off = 16; off; off >>= 1)
            m = fmaxf(m, __shfl_xor_sync(0xffffffffu, m, off));

        float e[4];
        float ssum = 0.0f;
#pragma unroll
        for (int o = 0; o < 4; ++o) {
            const int jj = lane + 32 * o;
            e[o] = (jj < IN) ? __expf(z[o] - m) : 0.0f;
            ssum += e[o];
        }
#pragma unroll
        for (int off = 16; off; off >>= 1)
            ssum += __shfl_xor_sync(0xffffffffu, ssum, off);

        const float r = __fdividef(1.0f, ssum);
        float* yo = ys + (size_t)i * IN;
#pragma unroll
        for (int o = 0; o < 4; ++o) {
            const int jj = lane + 32 * o;
            if (jj < IN) yo[jj] = e[o] * r;
        }
    }
}

// ============================================================================
// inputs (metadata order): s[SEQ*IN] f32, initialState[HID] f32,
//                          Wx[HID*IN] f32, Wh[HID*HID] f32, Wy[IN*HID] f32
// output: t_final[HID] then ys[SEQ*IN], float32
// ============================================================================
extern "C" void kernel_launch(void* const* d_in, const int* in_sizes, int n_in,
                              void* d_out, int out_size)
{
    const float* s    = (const float*)d_in[0];
    const float* init = (const float*)d_in[1];
    const float* Wx   = (const float*)d_in[2];
    const float* Wh   = (const float*)d_in[3];
    const float* Wy   = (const float*)d_in[4];
    float* out = (float*)d_out;

    phase1_kernel<<<SEQ / 32, 32>>>(s, Wx);
    phase2_kernel<<<1, 64>>>(init, Wh, out);          // writes out[0..39] + g_T
    phase3_kernel<<<2048, 256>>>(Wy, out + HID);      // writes ys
}

// round 4
// speedup vs baseline: 1.4237x; 1.0677x over previous
#include <cuda_runtime.h>

#define SEQ 262144
#define IN  100
#define HID 40

// scratch (allocation-free rule: __device__ globals). g_A padded so the
// phase-2 prefetch ring (depth 8) can read past the end unguarded.
__device__ float g_A[SEQ * HID + 8 * HID + 64];   // a_i = Wx @ x_i
__device__ float g_T[SEQ * HID];                  // t_i trace for phase 3

typedef unsigned long long u64;

__device__ __forceinline__ u64 pack2(float lo, float hi) {
    u64 r; asm("mov.b64 %0, {%1,%2};" : "=l"(r) : "f"(lo), "f"(hi)); return r;
}
__device__ __forceinline__ void unpack2(u64 v, float& lo, float& hi) {
    asm("mov.b64 {%0,%1}, %2;" : "=f"(lo), "=f"(hi) : "l"(v));
}
__device__ __forceinline__ u64 fma2(u64 a, u64 b, u64 c) {
    u64 d; asm("fma.rn.f32x2 %0, %1, %2, %3;" : "=l"(d) : "l"(a), "l"(b), "l"(c)); return d;
}
__device__ __forceinline__ u64 add2(u64 a, u64 b) {
    u64 d; asm("add.rn.f32x2 %0, %1, %2;" : "=l"(d) : "l"(a), "l"(b)); return d;
}
__device__ __forceinline__ float hadd2(u64 v) {
    float lo, hi; unpack2(v, lo, hi); return lo + hi;
}
__device__ __forceinline__ float tanh_approx(float x) {
    float r; asm("tanh.approx.f32 %0, %1;" : "=f"(r) : "f"(x)); return r;
}

// ============================================================================
// Phase 1: g_A[i][j] = sum_k Wx[j][k] * s[i][k]   (fully parallel)
// ============================================================================
__global__ void __launch_bounds__(32) phase1_kernel(
    const float* __restrict__ s, const float* __restrict__ Wx)
{
    __shared__ __align__(16) float wx[HID * IN];   // 16000 B
    __shared__ u64 xs[IN / 2][32];                 // 12800 B

    const int lane = threadIdx.x;

    const float4* wsrc = (const float4*)Wx;
    float4* wdst = (float4*)wx;
    for (int t = lane; t < (HID * IN) / 4; t += 32) wdst[t] = wsrc[t];

    const int i = blockIdx.x * 32 + lane;
    const float4* xr = (const float4*)(s + (size_t)i * IN);
#pragma unroll
    for (int c = 0; c < IN / 4; ++c) {
        float4 v = xr[c];
        xs[2 * c][lane]     = pack2(v.x, v.y);
        xs[2 * c + 1][lane] = pack2(v.z, v.w);
    }
    __syncthreads();

    float* Ao = g_A + (size_t)i * HID;
#pragma unroll 1
    for (int j = 0; j < HID; ++j) {
        const u64* wrow = (const u64*)(wx + j * IN);
        u64 acc[4] = {0, 0, 0, 0};
#pragma unroll
        for (int k = 0; k < IN / 2; ++k) {
            acc[k & 3] = fma2(wrow[k], xs[k][lane], acc[k & 3]);
        }
        Ao[j] = hadd2(add2(add2(acc[0], acc[1]), add2(acc[2], acc[3])));
    }
}

// ============================================================================
// Phase 2: serial recurrence. 64 threads (2 warps), thread j < 40 owns
// output j. This round: unroll capped at 2 (kill register spill), named
// scalar loads, a-term moved to chain tail with depth-8 prefetch ring,
// single-MUFU tanh.approx.
// ============================================================================
__global__ void __launch_bounds__(64, 1) phase2_kernel(
    const float* __restrict__ init, const float* __restrict__ Wh,
    float* __restrict__ tfinal)
{
    __shared__ __align__(16) float tsh[2][64];

    const int j  = threadIdx.x;
    const int jr = (j < HID) ? j : 0;          // clamp for OOB-safe loads
    const bool act = (j < HID);

    // preload Wh row jr into registers (no prescale)
    u64 wh[HID / 2];
    const float2* wr = (const float2*)(Wh + jr * HID);
#pragma unroll
    for (int p = 0; p < HID / 2; ++p) {
        float2 w = wr[p];
        wh[p] = pack2(w.x, w.y);
    }

    tsh[0][j] = act ? init[j] : 0.0f;
    tsh[1][j] = 0.0f;

    // prefetch ring for a, depth 8 (g_A padded; no bounds checks)
    const float* ap = g_A + jr;
    float a[8];
#pragma unroll
    for (int d = 0; d < 8; ++d) a[d] = ap[d * HID];
    ap += 8 * HID;

    __syncthreads();

    float outv = tsh[0][j];
    float* gT = g_T + jr;

#pragma unroll 2
    for (int i = 0; i < SEQ; ++i) {
        const int rb   = i & 1;
        const int slot = i & 7;
        const ulonglong2* tb = (const ulonglong2*)tsh[rb];

        // ---- batched loads: 10x LDS.128 into named scalars ----
        ulonglong2 p0 = tb[0], p1 = tb[1], p2 = tb[2], p3 = tb[3], p4 = tb[4];
        ulonglong2 p5 = tb[5], p6 = tb[6], p7 = tb[7], p8 = tb[8], p9 = tb[9];

        // prefetch a_{i+8} (off critical path)
        float anew = ap[0];
        ap += HID;

        // ---- 4 independent fma2 chains, depth 5 ----
        u64 acc0 = fma2(wh[0],  p0.x, 0ull);
        u64 acc1 = fma2(wh[1],  p0.y, 0ull);
        u64 acc2 = fma2(wh[2],  p1.x, 0ull);
        u64 acc3 = fma2(wh[3],  p1.y, 0ull);
        acc0 = fma2(wh[4],  p2.x, acc0);
        acc1 = fma2(wh[5],  p2.y, acc1);
        acc2 = fma2(wh[6],  p3.x, acc2);
        acc3 = fma2(wh[7],  p3.y, acc3);
        acc0 = fma2(wh[8],  p4.x, acc0);
        acc1 = fma2(wh[9],  p4.y, acc1);
        acc2 = fma2(wh[10], p5.x, acc2);
        acc3 = fma2(wh[11], p5.y, acc3);
        acc0 = fma2(wh[12], p6.x, acc0);
        acc1 = fma2(wh[13], p6.y, acc1);
        acc2 = fma2(wh[14], p7.x, acc2);
        acc3 = fma2(wh[15], p7.y, acc3);
        acc0 = fma2(wh[16], p8.x, acc0);
        acc1 = fma2(wh[17], p8.y, acc1);
        acc2 = fma2(wh[18], p9.x, acc2);
        acc3 = fma2(wh[19], p9.y, acc3);

        float lo, hi;
        unpack2(add2(add2(acc0, acc1), add2(acc2, acc3)), lo, hi);
        float v = (lo + hi) + a[slot];
        a[slot] = anew;

        outv = tanh_approx(v);

        tsh[rb ^ 1][j] = outv;        // STS first (barrier gates on this)
        if (act) gT[(size_t)i * HID] = outv;   // STG off the sync path

        __syncthreads();
    }

    if (act) tfinal[j] = outv;
}

// ============================================================================
// Phase 3: y_i = softmax(Wy @ t_i)  (fully parallel, one warp per timestep)
// ============================================================================
#define WYPAD 42
__global__ void __launch_bounds__(256) phase3_kernel(
    const float* __restrict__ Wy, float* __restrict__ ys)
{
    __shared__ __align__(8) float wy[IN * WYPAD];

    const int tid = threadIdx.x;
    for (int t = tid; t < IN * HID; t += 256) {
        int jrow = t / HID, kr = t % HID;
        wy[jrow * WYPAD + kr] = Wy[t];
    }
    __syncthreads();

    const int lane = tid & 31;
    const int warp = blockIdx.x * 8 + (tid >> 5);
    const int nwarp = gridDim.x * 8;

    for (int i = warp; i < SEQ; i += nwarp) {
        const ulonglong2* tp = (const ulonglong2*)(g_T + (size_t)i * HID);
        u64 t2[HID / 2];
#pragma unroll
        for (int p = 0; p < 10; ++p) {
            ulonglong2 v = tp[p];
            t2[2 * p]     = v.x;
            t2[2 * p + 1] = v.y;
        }

        float z[4];
#pragma unroll
        for (int o = 0; o < 4; ++o) {
            const int jj = lane + 32 * o;
            if (jj < IN) {
                const u64* wrow = (const u64*)(wy + jj * WYPAD);
                u64 acc[4] = {0, 0, 0, 0};
#pragma unroll
                for (int p = 0; p < HID / 2; ++p)
                    acc[p & 3] = fma2(wrow[p], t2[p], acc[p & 3]);
                z[o] = hadd2(add2(add2(acc[0], acc[1]), add2(acc[2], acc[3])));
            } else {
                z[o] = -1e30f;
            }
        }

        float m = fmaxf(fmaxf(z[0], z[1]), fmaxf(z[2], z[3]));
#pragma unroll
        for (int off = 16; off; off >>= 1)
            m = fmaxf(m, __shfl_xor_sync(0xffffffffu, m, off));

        float e[4];
        float ssum = 0.0f;
#pragma unroll
        for (int o = 0; o < 4; ++o) {
            const int jj = lane + 32 * o;
            e[o] = (jj < IN) ? __expf(z[o] - m) : 0.0f;
            ssum += e[o];
        }
#pragma unroll
        for (int off = 16; off; off >>= 1)
            ssum += __shfl_xor_sync(0xffffffffu, ssum, off);

        const float r = __fdividef(1.0f, ssum);
        float* yo = ys + (size_t)i * IN;
#pragma unroll
        for (int o = 0; o < 4; ++o) {
            const int jj = lane + 32 * o;
            if (jj < IN) yo[jj] = e[o] * r;
        }
    }
}

// ============================================================================
// inputs (metadata order): s[SEQ*IN] f32, initialState[HID] f32,
//                          Wx[HID*IN] f32, Wh[HID*HID] f32, Wy[IN*HID] f32
// output: t_final[HID] then ys[SEQ*IN], float32
// ============================================================================
extern "C" void kernel_launch(void* const* d_in, const int* in_sizes, int n_in,
                              void* d_out, int out_size)
{
    const float* s    = (const float*)d_in[0];
    const float* init = (const float*)d_in[1];
    const float* Wx   = (const float*)d_in[2];
    const float* Wh   = (const float*)d_in[3];
    const float* Wy   = (const float*)d_in[4];
    float* out = (float*)d_out;

    phase1_kernel<<<SEQ / 32, 32>>>(s, Wx);
    phase2_kernel<<<1, 64>>>(init, Wh, out);          // writes out[0..39] + g_T
    phase3_kernel<<<2048, 256>>>(Wy, out + HID);      // writes ys
}